// round 3
// baseline (speedup 1.0000x reference)
#include <cuda_runtime.h>

// Problem constants
#define B_  4
#define S_  2048
#define D_  1024
#define H_  16
#define DK_ 64
#define M_  (B_*S_)   // 8192

// Scratch (device globals — no allocations allowed)
__device__ float g_Q[(size_t)B_*H_*S_*DK_];
__device__ float g_K[(size_t)B_*H_*S_*DK_];
__device__ float g_V[(size_t)B_*H_*S_*DK_];
__device__ float g_A[(size_t)B_*S_*D_];

// ============================================================================
// SGEMM core: C = A @ W^T.  A:[M,K] row-major, W:[N,K] row-major.
// MODE 0: C plain row-major [M,N].
// MODE 1: split-heads epilogue: C[((b*H + h)*S + s)*64 + dk], m=b*S+s, n=h*64+dk.
// 128x128 block, BK=16, 256 threads, 8x8 per thread, fp32, double-buffered smem.
// ============================================================================
#define BM 128
#define BN 128
#define BKG 16

template<int MODE>
__device__ __forceinline__
void gemm_core(const float* __restrict__ A, const float* __restrict__ W,
               float* __restrict__ C, int M, int N, int K,
               int bx, int by) {
    __shared__ float As[2][BKG][BM + 4];
    __shared__ float Bs[2][BKG][BN + 4];

    const int m0 = by * BM;
    const int n0 = bx * BN;
    const int tid = threadIdx.x;
    const int tx = tid & 15;        // 0..15 -> 8 cols each
    const int ty = tid >> 4;        // 0..15 -> 8 rows each

    // Per-thread gmem load coords (2 float4 from A, 2 from W per k-tile)
    const int r0  = tid >> 2;              // rows 0..63   (it=0) / +64 (it=1)
    const int c40 = (tid & 3) << 2;        // 0,4,8,12

    float acc[8][8];
#pragma unroll
    for (int i = 0; i < 8; ++i)
#pragma unroll
        for (int j = 0; j < 8; ++j) acc[i][j] = 0.f;

    const int NT = K / BKG;

    // Prologue: load tile 0 into buffer 0
#pragma unroll
    for (int it = 0; it < 2; ++it) {
        int r = r0 + it * 64;
        float4 av = *(const float4*)(A + (size_t)(m0 + r) * K + c40);
        As[0][c40 + 0][r] = av.x; As[0][c40 + 1][r] = av.y;
        As[0][c40 + 2][r] = av.z; As[0][c40 + 3][r] = av.w;
        float4 bv = *(const float4*)(W + (size_t)(n0 + r) * K + c40);
        Bs[0][c40 + 0][r] = bv.x; Bs[0][c40 + 1][r] = bv.y;
        Bs[0][c40 + 2][r] = bv.z; Bs[0][c40 + 3][r] = bv.w;
    }
    __syncthreads();

    for (int kt = 0; kt < NT; ++kt) {
        const int cur = kt & 1;

        // Prefetch next tile gmem -> regs
        float4 pa[2], pb[2];
        if (kt + 1 < NT) {
            const int k0 = (kt + 1) * BKG;
#pragma unroll
            for (int it = 0; it < 2; ++it) {
                int r = r0 + it * 64;
                pa[it] = *(const float4*)(A + (size_t)(m0 + r) * K + k0 + c40);
                pb[it] = *(const float4*)(W + (size_t)(n0 + r) * K + k0 + c40);
            }
        }

        // Compute from current buffer
#pragma unroll
        for (int kk = 0; kk < BKG; ++kk) {
            float af[8], bf[8];
            *(float4*)(af)     = *(const float4*)&As[cur][kk][ty * 8];
            *(float4*)(af + 4) = *(const float4*)&As[cur][kk][ty * 8 + 4];
            *(float4*)(bf)     = *(const float4*)&Bs[cur][kk][tx * 8];
            *(float4*)(bf + 4) = *(const float4*)&Bs[cur][kk][tx * 8 + 4];
#pragma unroll
            for (int i = 0; i < 8; ++i)
#pragma unroll
                for (int j = 0; j < 8; ++j)
                    acc[i][j] += af[i] * bf[j];
        }

        // Store prefetched tile to the other buffer
        if (kt + 1 < NT) {
            const int nxt = cur ^ 1;
#pragma unroll
            for (int it = 0; it < 2; ++it) {
                int r = r0 + it * 64;
                As[nxt][c40 + 0][r] = pa[it].x; As[nxt][c40 + 1][r] = pa[it].y;
                As[nxt][c40 + 2][r] = pa[it].z; As[nxt][c40 + 3][r] = pa[it].w;
                Bs[nxt][c40 + 0][r] = pb[it].x; Bs[nxt][c40 + 1][r] = pb[it].y;
                Bs[nxt][c40 + 2][r] = pb[it].z; Bs[nxt][c40 + 3][r] = pb[it].w;
            }
            __syncthreads();
        }
    }

    // Epilogue
    const int n = n0 + tx * 8;
#pragma unroll
    for (int i = 0; i < 8; ++i) {
        int m = m0 + ty * 8 + i;
        float* p;
        if (MODE == 0) {
            p = C + (size_t)m * N + n;
        } else {
            int b  = m >> 11;         // / S_
            int s  = m & (S_ - 1);
            int h  = n >> 6;          // / DK_
            int dk = n & 63;
            p = C + ((size_t)((b * H_ + h) * S_ + s)) * DK_ + dk;
        }
        *(float4*)p       = make_float4(acc[i][0], acc[i][1], acc[i][2], acc[i][3]);
        *(float4*)(p + 4) = make_float4(acc[i][4], acc[i][5], acc[i][6], acc[i][7]);
    }
}

// Fused Q/K/V projections: blockIdx.z selects which projection.
__global__ __launch_bounds__(256)
void gemm_qkv(const float* __restrict__ q, const float* __restrict__ k,
              const float* __restrict__ v,
              const float* __restrict__ Wq, const float* __restrict__ Wk,
              const float* __restrict__ Wv,
              float* __restrict__ Qo, float* __restrict__ Ko,
              float* __restrict__ Vo) {
    const float* A = (blockIdx.z == 0) ? q  : (blockIdx.z == 1) ? k  : v;
    const float* W = (blockIdx.z == 0) ? Wq : (blockIdx.z == 1) ? Wk : Wv;
    float*       C = (blockIdx.z == 0) ? Qo : (blockIdx.z == 1) ? Ko : Vo;
    gemm_core<1>(A, W, C, M_, D_, D_, blockIdx.x, blockIdx.y);
}

__global__ __launch_bounds__(256)
void gemm_out(const float* __restrict__ A, const float* __restrict__ W,
              float* __restrict__ C) {
    gemm_core<0>(A, W, C, M_, D_, D_, blockIdx.x, blockIdx.y);
}

// ============================================================================
// Flash attention, fp32, causal. 64 q-rows per block, 64-col kv tiles.
// Q/K staged transposed [dk][row] (stride 68), scores reuse the K buffer,
// V row-major [j][dk] (stride 64). 256 threads.
// Softmax/PV ownership: row r = tid/4, quarter c = tid%4 (16 dk values each).
// Output written directly to [B,S,D] layout.
// ============================================================================
#define QT 64
#define KT 64
#define PAD_ 68
#define SM_Q   (QT * PAD_)
#define SM_KS  (KT * PAD_)
#define SM_V   (KT * 64)
#define ATT_SMEM ((SM_Q + SM_KS + SM_V) * (int)sizeof(float))

// 64x64 tile, global rows contiguous (ld=64) -> smem transposed dst[dk*PAD_+row]
__device__ __forceinline__ void load_tile_T(float* dst, const float* __restrict__ src) {
    const int tid = threadIdx.x;
#pragma unroll
    for (int it = 0; it < 4; ++it) {
        int f   = tid + it * 256;          // float4 id 0..1023
        int row = f >> 4;                  // 0..63
        int dk4 = (f & 15) << 2;           // 0..60
        float4 v = *(const float4*)(src + row * 64 + dk4);
        dst[(dk4 + 0) * PAD_ + row] = v.x;
        dst[(dk4 + 1) * PAD_ + row] = v.y;
        dst[(dk4 + 2) * PAD_ + row] = v.z;
        dst[(dk4 + 3) * PAD_ + row] = v.w;
    }
}

__device__ __forceinline__ void load_tile(float* dst, const float* __restrict__ src) {
    const int tid = threadIdx.x;
#pragma unroll
    for (int it = 0; it < 4; ++it) {
        int f = tid + it * 256;
        ((float4*)dst)[f] = ((const float4*)src)[f];
    }
}

__global__ __launch_bounds__(256)
void attn_kernel(const float* __restrict__ Q, const float* __restrict__ K,
                 const float* __restrict__ V, float* __restrict__ Out) {
    extern __shared__ float sm[];
    float* sQ  = sm;                   // [64][PAD_] transposed
    float* sKS = sm + SM_Q;            // K transposed, then P row-major [m][PAD_]
    float* sV  = sm + SM_Q + SM_KS;    // [64][64]

    const int qt  = blockIdx.x;        // 0..31
    const int bh  = blockIdx.y;        // 0..63
    const int tid = threadIdx.x;
    const int tx = tid & 15, ty = tid >> 4;   // phase-1 layout (4x4 scores)
    const int r  = tid >> 2, c = tid & 3;     // phase-2/3 layout

    const float* Qb = Q + ((size_t)bh * S_ + qt * QT) * DK_;
    load_tile_T(sQ, Qb);

    float m_i = -1e30f, l_i = 0.f;
    float Oacc[16];
#pragma unroll
    for (int i = 0; i < 16; ++i) Oacc[i] = 0.f;

    for (int t = 0; t <= qt; ++t) {
        __syncthreads();   // prev-iter readers done (t=0: Q-load visibility)
        load_tile_T(sKS, K + ((size_t)bh * S_ + t * KT) * DK_);
        load_tile  (sV,  V + ((size_t)bh * S_ + t * KT) * DK_);
        __syncthreads();

        // ---- Phase 1: scores 4x4 per thread ----
        float sc[4][4];
#pragma unroll
        for (int i = 0; i < 4; ++i)
#pragma unroll
            for (int j = 0; j < 4; ++j) sc[i][j] = 0.f;

#pragma unroll 8
        for (int k = 0; k < 64; ++k) {
            float4 qf = *(const float4*)&sQ [k * PAD_ + ty * 4];
            float4 kf = *(const float4*)&sKS[k * PAD_ + tx * 4];
            sc[0][0] += qf.x * kf.x; sc[0][1] += qf.x * kf.y; sc[0][2] += qf.x * kf.z; sc[0][3] += qf.x * kf.w;
            sc[1][0] += qf.y * kf.x; sc[1][1] += qf.y * kf.y; sc[1][2] += qf.y * kf.z; sc[1][3] += qf.y * kf.w;
            sc[2][0] += qf.z * kf.x; sc[2][1] += qf.z * kf.y; sc[2][2] += qf.z * kf.z; sc[2][3] += qf.z * kf.w;
            sc[3][0] += qf.w * kf.x; sc[3][1] += qf.w * kf.y; sc[3][2] += qf.w * kf.z; sc[3][3] += qf.w * kf.w;
        }
        __syncthreads();   // everyone finished reading K from sKS

        const float scale = 0.125f;   // 1/sqrt(64)
#pragma unroll
        for (int i = 0; i < 4; ++i) {
            int lr = ty * 4 + i;
#pragma unroll
            for (int j = 0; j < 4; ++j) {
                float s = sc[i][j] * scale;
                if (t == qt && (tx * 4 + j) > lr) s = -1e9f;
                sc[i][j] = s;
            }
            *(float4*)&sKS[lr * PAD_ + tx * 4] =
                make_float4(sc[i][0], sc[i][1], sc[i][2], sc[i][3]);
        }
        __syncthreads();

        // ---- Phase 2: online softmax (row r, cols c*16..c*16+15) ----
        float pj[16];
        float mx = -1e30f;
        const int sb = r * PAD_ + c * 16;
#pragma unroll
        for (int jj = 0; jj < 16; ++jj) { pj[jj] = sKS[sb + jj]; mx = fmaxf(mx, pj[jj]); }
        mx = fmaxf(mx, __shfl_xor_sync(0xffffffffu, mx, 1));
        mx = fmaxf(mx, __shfl_xor_sync(0xffffffffu, mx, 2));
        float newm = fmaxf(m_i, mx);
        float sum = 0.f;
#pragma unroll
        for (int jj = 0; jj < 16; ++jj) {
            float p = __expf(pj[jj] - newm);
            pj[jj] = p; sum += p;
        }
        sum += __shfl_xor_sync(0xffffffffu, sum, 1);
        sum += __shfl_xor_sync(0xffffffffu, sum, 2);
        float alpha = __expf(m_i - newm);
        l_i = l_i * alpha + sum;
        m_i = newm;
#pragma unroll
        for (int i = 0; i < 16; ++i) Oacc[i] *= alpha;
#pragma unroll
        for (int jj = 0; jj < 16; jj += 4)
            *(float4*)&sKS[sb + jj] = make_float4(pj[jj], pj[jj+1], pj[jj+2], pj[jj+3]);
        __syncthreads();

        // ---- Phase 3: O += P @ V ----
        const int vb = c * 16;
#pragma unroll 8
        for (int j = 0; j < 64; ++j) {
            float p = sKS[r * PAD_ + j];
            float4 v0 = *(const float4*)&sV[j * 64 + vb +  0];
            float4 v1 = *(const float4*)&sV[j * 64 + vb +  4];
            float4 v2 = *(const float4*)&sV[j * 64 + vb +  8];
            float4 v3 = *(const float4*)&sV[j * 64 + vb + 12];
            Oacc[ 0] += p * v0.x; Oacc[ 1] += p * v0.y; Oacc[ 2] += p * v0.z; Oacc[ 3] += p * v0.w;
            Oacc[ 4] += p * v1.x; Oacc[ 5] += p * v1.y; Oacc[ 6] += p * v1.z; Oacc[ 7] += p * v1.w;
            Oacc[ 8] += p * v2.x; Oacc[ 9] += p * v2.y; Oacc[10] += p * v2.z; Oacc[11] += p * v2.w;
            Oacc[12] += p * v3.x; Oacc[13] += p * v3.y; Oacc[14] += p * v3.z; Oacc[15] += p * v3.w;
        }
    }

    // Epilogue: write to [B,S,D]
    float inv = 1.f / l_i;
    int b = bh >> 4, h = bh & 15;
    int qrow = qt * QT + r;
    float* o = Out + ((size_t)(b * S_ + qrow)) * D_ + h * DK_ + c * 16;
#pragma unroll
    for (int i = 0; i < 16; i += 4)
        *(float4*)(o + i) = make_float4(Oacc[i] * inv, Oacc[i+1] * inv,
                                        Oacc[i+2] * inv, Oacc[i+3] * inv);
}

// ============================================================================
// Launch
// ============================================================================
extern "C" void kernel_launch(void* const* d_in, const int* in_sizes, int n_in,
                              void* d_out, int out_size) {
    const float* q  = (const float*)d_in[0];
    const float* k  = (const float*)d_in[1];
    const float* v  = (const float*)d_in[2];
    // d_in[3] = mask (causal, known statically) — unused
    const float* Wq = (const float*)d_in[4];
    const float* Wk = (const float*)d_in[5];
    const float* Wv = (const float*)d_in[6];
    const float* Wo = (const float*)d_in[7];
    float* out = (float*)d_out;

    float *pQ, *pK, *pV, *pA;
    cudaGetSymbolAddress((void**)&pQ, g_Q);
    cudaGetSymbolAddress((void**)&pK, g_K);
    cudaGetSymbolAddress((void**)&pV, g_V);
    cudaGetSymbolAddress((void**)&pA, g_A);

    // Fused Q/K/V projections (one launch, z selects projection)
    dim3 qkv_grid(D_ / BN, M_ / BM, 3);   // (8, 64, 3)
    gemm_qkv<<<qkv_grid, 256>>>(q, k, v, Wq, Wk, Wv, pQ, pK, pV);

    cudaFuncSetAttribute(attn_kernel,
                         cudaFuncAttributeMaxDynamicSharedMemorySize, ATT_SMEM);
    attn_kernel<<<dim3(S_ / QT, B_ * H_), 256, ATT_SMEM>>>(pQ, pK, pV, pA);

    dim3 ogrid(D_ / BN, M_ / BM);         // (8, 64)
    gemm_out<<<ogrid, 256>>>(pA, Wo, out);
}

// round 4
// speedup vs baseline: 1.2510x; 1.2510x over previous
#include <cuda_runtime.h>
#include <cstdint>

// Problem constants
#define B_  4
#define S_  2048
#define D_  1024
#define H_  16
#define DK_ 64
#define M_  (B_*S_)   // 8192

// Scratch (device globals — no allocations allowed)
__device__ float g_Q[(size_t)B_*H_*S_*DK_];
__device__ float g_K[(size_t)B_*H_*S_*DK_];
__device__ float g_V[(size_t)B_*H_*S_*DK_];
__device__ float g_A[(size_t)B_*S_*D_];

// ============================================================================
// TF32 tensor-core GEMM: C = A @ W^T.
// A:[M,K] row-major, W:[N,K] row-major (nn.Linear weight layout).
// mma.sync.m16n8k8.row.col: A row-major frag, B col-major frag == W row-major.
// Block 128x128, BK=16, 256 thr (8 warps, warp tile 64x32), double-buffered.
// tf32 rounding (cvt.rna) applied once at smem staging; fp32 accumulate.
// MODE 0: C row-major [M,N]. MODE 1: split-heads epilogue.
// ============================================================================
#define BM 128
#define BN 128
#define BKG 16
#define LDS_ (BKG + 4)   // 20 floats: conflict-free for fragment pattern

__device__ __forceinline__ uint32_t f2tf32(float f) {
    uint32_t u;
    asm("cvt.rna.tf32.f32 %0, %1;" : "=r"(u) : "f"(f));
    return u;
}

__device__ __forceinline__ void mma_tf32(float d[4], const uint32_t a[4],
                                         const uint32_t b[2]) {
    asm volatile(
        "mma.sync.aligned.m16n8k8.row.col.f32.tf32.tf32.f32 "
        "{%0,%1,%2,%3}, {%4,%5,%6,%7}, {%8,%9}, {%0,%1,%2,%3};\n"
        : "+f"(d[0]), "+f"(d[1]), "+f"(d[2]), "+f"(d[3])
        : "r"(a[0]), "r"(a[1]), "r"(a[2]), "r"(a[3]),
          "r"(b[0]), "r"(b[1]));
}

template<int MODE>
__device__ __forceinline__
void gemm_core(const float* __restrict__ A, const float* __restrict__ W,
               float* __restrict__ C, int M, int N, int K,
               int bx, int by) {
    __shared__ uint32_t As[2][BM][LDS_];
    __shared__ uint32_t Bs[2][BN][LDS_];

    const int m0 = by * BM;
    const int n0 = bx * BN;
    const int tid = threadIdx.x;
    const int wid = tid >> 5;
    const int lane = tid & 31;
    const int qr = lane >> 2;      // 0..7
    const int ql = lane & 3;       // 0..3

    const int wm0 = (wid & 1) * 64;   // warp m-origin in block
    const int wn0 = (wid >> 1) * 32;  // warp n-origin in block

    // Global staging coords: thread loads 1 float4 per 64-row half, per array
    const int grow = tid >> 2;             // 0..63 (+64 second half)
    const int gc4  = (tid & 3) << 2;       // 0,4,8,12

    float acc[4][4][4];                    // [mt][nt][frag]
#pragma unroll
    for (int mt = 0; mt < 4; ++mt)
#pragma unroll
        for (int nt = 0; nt < 4; ++nt)
#pragma unroll
            for (int i = 0; i < 4; ++i) acc[mt][nt][i] = 0.f;

    const int NT = K / BKG;

    // Prologue: stage tile 0 (tf32-rounded)
#pragma unroll
    for (int it = 0; it < 2; ++it) {
        int r = grow + it * 64;
        float4 av = *(const float4*)(A + (size_t)(m0 + r) * K + gc4);
        As[0][r][gc4 + 0] = f2tf32(av.x); As[0][r][gc4 + 1] = f2tf32(av.y);
        As[0][r][gc4 + 2] = f2tf32(av.z); As[0][r][gc4 + 3] = f2tf32(av.w);
        float4 bv = *(const float4*)(W + (size_t)(n0 + r) * K + gc4);
        Bs[0][r][gc4 + 0] = f2tf32(bv.x); Bs[0][r][gc4 + 1] = f2tf32(bv.y);
        Bs[0][r][gc4 + 2] = f2tf32(bv.z); Bs[0][r][gc4 + 3] = f2tf32(bv.w);
    }
    __syncthreads();

    for (int kt = 0; kt < NT; ++kt) {
        const int cur = kt & 1;

        // Prefetch next tile gmem -> regs
        float4 pa[2], pb[2];
        if (kt + 1 < NT) {
            const int k0 = (kt + 1) * BKG;
#pragma unroll
            for (int it = 0; it < 2; ++it) {
                int r = grow + it * 64;
                pa[it] = *(const float4*)(A + (size_t)(m0 + r) * K + k0 + gc4);
                pb[it] = *(const float4*)(W + (size_t)(n0 + r) * K + k0 + gc4);
            }
        }

        // Compute: 2 k-steps of 8
#pragma unroll
        for (int ks = 0; ks < 2; ++ks) {
            const int k0 = ks * 8;
            uint32_t af[4][4], bf[4][2];
#pragma unroll
            for (int mt = 0; mt < 4; ++mt) {
                int rb = wm0 + mt * 16 + qr;
                af[mt][0] = As[cur][rb    ][k0 + ql];
                af[mt][1] = As[cur][rb + 8][k0 + ql];
                af[mt][2] = As[cur][rb    ][k0 + ql + 4];
                af[mt][3] = As[cur][rb + 8][k0 + ql + 4];
            }
#pragma unroll
            for (int nt = 0; nt < 4; ++nt) {
                int nb = wn0 + nt * 8 + qr;
                bf[nt][0] = Bs[cur][nb][k0 + ql];
                bf[nt][1] = Bs[cur][nb][k0 + ql + 4];
            }
#pragma unroll
            for (int mt = 0; mt < 4; ++mt)
#pragma unroll
                for (int nt = 0; nt < 4; ++nt)
                    mma_tf32(acc[mt][nt], af[mt], bf[nt]);
        }

        // Store prefetched tile to the other buffer
        if (kt + 1 < NT) {
            const int nxt = cur ^ 1;
#pragma unroll
            for (int it = 0; it < 2; ++it) {
                int r = grow + it * 64;
                As[nxt][r][gc4 + 0] = f2tf32(pa[it].x);
                As[nxt][r][gc4 + 1] = f2tf32(pa[it].y);
                As[nxt][r][gc4 + 2] = f2tf32(pa[it].z);
                As[nxt][r][gc4 + 3] = f2tf32(pa[it].w);
                Bs[nxt][r][gc4 + 0] = f2tf32(pb[it].x);
                Bs[nxt][r][gc4 + 1] = f2tf32(pb[it].y);
                Bs[nxt][r][gc4 + 2] = f2tf32(pb[it].z);
                Bs[nxt][r][gc4 + 3] = f2tf32(pb[it].w);
            }
            __syncthreads();
        }
    }

    // Epilogue: c0,c1 at (row, col), (row, col+1); c2,c3 at (row+8, ...)
#pragma unroll
    for (int mt = 0; mt < 4; ++mt) {
#pragma unroll
        for (int nt = 0; nt < 4; ++nt) {
#pragma unroll
            for (int half = 0; half < 2; ++half) {
                int m = m0 + wm0 + mt * 16 + qr + half * 8;
                int n = n0 + wn0 + nt * 8 + ql * 2;
                float* p;
                if (MODE == 0) {
                    p = C + (size_t)m * N + n;
                } else {
                    int b  = m >> 11;          // / S_
                    int s  = m & (S_ - 1);
                    int h  = n >> 6;           // / DK_
                    int dk = n & 63;
                    p = C + ((size_t)((b * H_ + h) * S_ + s)) * DK_ + dk;
                }
                *(float2*)p = make_float2(acc[mt][nt][half * 2],
                                          acc[mt][nt][half * 2 + 1]);
            }
        }
    }
}

// Fused Q/K/V projections: blockIdx.z selects which projection.
__global__ __launch_bounds__(256)
void gemm_qkv(const float* __restrict__ q, const float* __restrict__ k,
              const float* __restrict__ v,
              const float* __restrict__ Wq, const float* __restrict__ Wk,
              const float* __restrict__ Wv,
              float* __restrict__ Qo, float* __restrict__ Ko,
              float* __restrict__ Vo) {
    const float* A = (blockIdx.z == 0) ? q  : (blockIdx.z == 1) ? k  : v;
    const float* W = (blockIdx.z == 0) ? Wq : (blockIdx.z == 1) ? Wk : Wv;
    float*       C = (blockIdx.z == 0) ? Qo : (blockIdx.z == 1) ? Ko : Vo;
    gemm_core<1>(A, W, C, M_, D_, D_, blockIdx.x, blockIdx.y);
}

__global__ __launch_bounds__(256)
void gemm_out(const float* __restrict__ A, const float* __restrict__ W,
              float* __restrict__ C) {
    gemm_core<0>(A, W, C, M_, D_, D_, blockIdx.x, blockIdx.y);
}

// ============================================================================
// Flash attention, fp32, causal (unchanged from passing R3 kernel).
// ============================================================================
#define QT 64
#define KT 64
#define PAD_ 68
#define SM_Q   (QT * PAD_)
#define SM_KS  (KT * PAD_)
#define SM_V   (KT * 64)
#define ATT_SMEM ((SM_Q + SM_KS + SM_V) * (int)sizeof(float))

__device__ __forceinline__ void load_tile_T(float* dst, const float* __restrict__ src) {
    const int tid = threadIdx.x;
#pragma unroll
    for (int it = 0; it < 4; ++it) {
        int f   = tid + it * 256;
        int row = f >> 4;
        int dk4 = (f & 15) << 2;
        float4 v = *(const float4*)(src + row * 64 + dk4);
        dst[(dk4 + 0) * PAD_ + row] = v.x;
        dst[(dk4 + 1) * PAD_ + row] = v.y;
        dst[(dk4 + 2) * PAD_ + row] = v.z;
        dst[(dk4 + 3) * PAD_ + row] = v.w;
    }
}

__device__ __forceinline__ void load_tile(float* dst, const float* __restrict__ src) {
    const int tid = threadIdx.x;
#pragma unroll
    for (int it = 0; it < 4; ++it) {
        int f = tid + it * 256;
        ((float4*)dst)[f] = ((const float4*)src)[f];
    }
}

__global__ __launch_bounds__(256)
void attn_kernel(const float* __restrict__ Q, const float* __restrict__ K,
                 const float* __restrict__ V, float* __restrict__ Out) {
    extern __shared__ float sm[];
    float* sQ  = sm;
    float* sKS = sm + SM_Q;
    float* sV  = sm + SM_Q + SM_KS;

    const int qt  = blockIdx.x;
    const int bh  = blockIdx.y;
    const int tid = threadIdx.x;
    const int tx = tid & 15, ty = tid >> 4;
    const int r  = tid >> 2, c = tid & 3;

    const float* Qb = Q + ((size_t)bh * S_ + qt * QT) * DK_;
    load_tile_T(sQ, Qb);

    float m_i = -1e30f, l_i = 0.f;
    float Oacc[16];
#pragma unroll
    for (int i = 0; i < 16; ++i) Oacc[i] = 0.f;

    for (int t = 0; t <= qt; ++t) {
        __syncthreads();
        load_tile_T(sKS, K + ((size_t)bh * S_ + t * KT) * DK_);
        load_tile  (sV,  V + ((size_t)bh * S_ + t * KT) * DK_);
        __syncthreads();

        float sc[4][4];
#pragma unroll
        for (int i = 0; i < 4; ++i)
#pragma unroll
            for (int j = 0; j < 4; ++j) sc[i][j] = 0.f;

#pragma unroll 8
        for (int k = 0; k < 64; ++k) {
            float4 qf = *(const float4*)&sQ [k * PAD_ + ty * 4];
            float4 kf = *(const float4*)&sKS[k * PAD_ + tx * 4];
            sc[0][0] += qf.x * kf.x; sc[0][1] += qf.x * kf.y; sc[0][2] += qf.x * kf.z; sc[0][3] += qf.x * kf.w;
            sc[1][0] += qf.y * kf.x; sc[1][1] += qf.y * kf.y; sc[1][2] += qf.y * kf.z; sc[1][3] += qf.y * kf.w;
            sc[2][0] += qf.z * kf.x; sc[2][1] += qf.z * kf.y; sc[2][2] += qf.z * kf.z; sc[2][3] += qf.z * kf.w;
            sc[3][0] += qf.w * kf.x; sc[3][1] += qf.w * kf.y; sc[3][2] += qf.w * kf.z; sc[3][3] += qf.w * kf.w;
        }
        __syncthreads();

        const float scale = 0.125f;
#pragma unroll
        for (int i = 0; i < 4; ++i) {
            int lr = ty * 4 + i;
#pragma unroll
            for (int j = 0; j < 4; ++j) {
                float s = sc[i][j] * scale;
                if (t == qt && (tx * 4 + j) > lr) s = -1e9f;
                sc[i][j] = s;
            }
            *(float4*)&sKS[lr * PAD_ + tx * 4] =
                make_float4(sc[i][0], sc[i][1], sc[i][2], sc[i][3]);
        }
        __syncthreads();

        float pj[16];
        float mx = -1e30f;
        const int sb = r * PAD_ + c * 16;
#pragma unroll
        for (int jj = 0; jj < 16; ++jj) { pj[jj] = sKS[sb + jj]; mx = fmaxf(mx, pj[jj]); }
        mx = fmaxf(mx, __shfl_xor_sync(0xffffffffu, mx, 1));
        mx = fmaxf(mx, __shfl_xor_sync(0xffffffffu, mx, 2));
        float newm = fmaxf(m_i, mx);
        float sum = 0.f;
#pragma unroll
        for (int jj = 0; jj < 16; ++jj) {
            float p = __expf(pj[jj] - newm);
            pj[jj] = p; sum += p;
        }
        sum += __shfl_xor_sync(0xffffffffu, sum, 1);
        sum += __shfl_xor_sync(0xffffffffu, sum, 2);
        float alpha = __expf(m_i - newm);
        l_i = l_i * alpha + sum;
        m_i = newm;
#pragma unroll
        for (int i = 0; i < 16; ++i) Oacc[i] *= alpha;
#pragma unroll
        for (int jj = 0; jj < 16; jj += 4)
            *(float4*)&sKS[sb + jj] = make_float4(pj[jj], pj[jj+1], pj[jj+2], pj[jj+3]);
        __syncthreads();

        const int vb = c * 16;
#pragma unroll 8
        for (int j = 0; j < 64; ++j) {
            float p = sKS[r * PAD_ + j];
            float4 v0 = *(const float4*)&sV[j * 64 + vb +  0];
            float4 v1 = *(const float4*)&sV[j * 64 + vb +  4];
            float4 v2 = *(const float4*)&sV[j * 64 + vb +  8];
            float4 v3 = *(const float4*)&sV[j * 64 + vb + 12];
            Oacc[ 0] += p * v0.x; Oacc[ 1] += p * v0.y; Oacc[ 2] += p * v0.z; Oacc[ 3] += p * v0.w;
            Oacc[ 4] += p * v1.x; Oacc[ 5] += p * v1.y; Oacc[ 6] += p * v1.z; Oacc[ 7] += p * v1.w;
            Oacc[ 8] += p * v2.x; Oacc[ 9] += p * v2.y; Oacc[10] += p * v2.z; Oacc[11] += p * v2.w;
            Oacc[12] += p * v3.x; Oacc[13] += p * v3.y; Oacc[14] += p * v3.z; Oacc[15] += p * v3.w;
        }
    }

    float inv = 1.f / l_i;
    int b = bh >> 4, h = bh & 15;
    int qrow = qt * QT + r;
    float* o = Out + ((size_t)(b * S_ + qrow)) * D_ + h * DK_ + c * 16;
#pragma unroll
    for (int i = 0; i < 16; i += 4)
        *(float4*)(o + i) = make_float4(Oacc[i] * inv, Oacc[i+1] * inv,
                                        Oacc[i+2] * inv, Oacc[i+3] * inv);
}

// ============================================================================
// Launch
// ============================================================================
extern "C" void kernel_launch(void* const* d_in, const int* in_sizes, int n_in,
                              void* d_out, int out_size) {
    const float* q  = (const float*)d_in[0];
    const float* k  = (const float*)d_in[1];
    const float* v  = (const float*)d_in[2];
    // d_in[3] = mask (causal, known statically) — unused
    const float* Wq = (const float*)d_in[4];
    const float* Wk = (const float*)d_in[5];
    const float* Wv = (const float*)d_in[6];
    const float* Wo = (const float*)d_in[7];
    float* out = (float*)d_out;

    float *pQ, *pK, *pV, *pA;
    cudaGetSymbolAddress((void**)&pQ, g_Q);
    cudaGetSymbolAddress((void**)&pK, g_K);
    cudaGetSymbolAddress((void**)&pV, g_V);
    cudaGetSymbolAddress((void**)&pA, g_A);

    dim3 qkv_grid(D_ / BN, M_ / BM, 3);   // (8, 64, 3)
    gemm_qkv<<<qkv_grid, 256>>>(q, k, v, Wq, Wk, Wv, pQ, pK, pV);

    cudaFuncSetAttribute(attn_kernel,
                         cudaFuncAttributeMaxDynamicSharedMemorySize, ATT_SMEM);
    attn_kernel<<<dim3(S_ / QT, B_ * H_), 256, ATT_SMEM>>>(pQ, pK, pV, pA);

    dim3 ogrid(D_ / BN, M_ / BM);         // (8, 64)
    gemm_out<<<ogrid, 256>>>(pA, Wo, out);
}

// round 5
// speedup vs baseline: 4.4632x; 3.5676x over previous
#include <cuda_runtime.h>
#include <cstdint>

// Problem constants
#define B_  4
#define S_  2048
#define D_  1024
#define H_  16
#define DK_ 64
#define M_  (B_*S_)   // 8192

// Scratch (device globals — no allocations allowed)
__device__ float g_Q[(size_t)B_*H_*S_*DK_];
__device__ float g_K[(size_t)B_*H_*S_*DK_];
__device__ float g_V[(size_t)B_*H_*S_*DK_];
__device__ float g_A[(size_t)B_*S_*D_];

__device__ __forceinline__ uint32_t f2tf32(float f) {
    uint32_t u;
    asm("cvt.rna.tf32.f32 %0, %1;" : "=r"(u) : "f"(f));
    return u;
}

__device__ __forceinline__ void mma_tf32(float d[4], const uint32_t a[4],
                                         const uint32_t b[2]) {
    asm volatile(
        "mma.sync.aligned.m16n8k8.row.col.f32.tf32.tf32.f32 "
        "{%0,%1,%2,%3}, {%4,%5,%6,%7}, {%8,%9}, {%0,%1,%2,%3};\n"
        : "+f"(d[0]), "+f"(d[1]), "+f"(d[2]), "+f"(d[3])
        : "r"(a[0]), "r"(a[1]), "r"(a[2]), "r"(a[3]),
          "r"(b[0]), "r"(b[1]));
}

// ============================================================================
// TF32 tensor-core GEMM: C = A @ W^T (unchanged from R4 passing kernel).
// ============================================================================
#define BM 128
#define BN 128
#define BKG 16
#define LDS_ (BKG + 4)

template<int MODE>
__device__ __forceinline__
void gemm_core(const float* __restrict__ A, const float* __restrict__ W,
               float* __restrict__ C, int M, int N, int K,
               int bx, int by) {
    __shared__ uint32_t As[2][BM][LDS_];
    __shared__ uint32_t Bs[2][BN][LDS_];

    const int m0 = by * BM;
    const int n0 = bx * BN;
    const int tid = threadIdx.x;
    const int wid = tid >> 5;
    const int lane = tid & 31;
    const int qr = lane >> 2;
    const int ql = lane & 3;

    const int wm0 = (wid & 1) * 64;
    const int wn0 = (wid >> 1) * 32;

    const int grow = tid >> 2;
    const int gc4  = (tid & 3) << 2;

    float acc[4][4][4];
#pragma unroll
    for (int mt = 0; mt < 4; ++mt)
#pragma unroll
        for (int nt = 0; nt < 4; ++nt)
#pragma unroll
            for (int i = 0; i < 4; ++i) acc[mt][nt][i] = 0.f;

    const int NT = K / BKG;

#pragma unroll
    for (int it = 0; it < 2; ++it) {
        int r = grow + it * 64;
        float4 av = *(const float4*)(A + (size_t)(m0 + r) * K + gc4);
        As[0][r][gc4 + 0] = f2tf32(av.x); As[0][r][gc4 + 1] = f2tf32(av.y);
        As[0][r][gc4 + 2] = f2tf32(av.z); As[0][r][gc4 + 3] = f2tf32(av.w);
        float4 bv = *(const float4*)(W + (size_t)(n0 + r) * K + gc4);
        Bs[0][r][gc4 + 0] = f2tf32(bv.x); Bs[0][r][gc4 + 1] = f2tf32(bv.y);
        Bs[0][r][gc4 + 2] = f2tf32(bv.z); Bs[0][r][gc4 + 3] = f2tf32(bv.w);
    }
    __syncthreads();

    for (int kt = 0; kt < NT; ++kt) {
        const int cur = kt & 1;

        float4 pa[2], pb[2];
        if (kt + 1 < NT) {
            const int k0 = (kt + 1) * BKG;
#pragma unroll
            for (int it = 0; it < 2; ++it) {
                int r = grow + it * 64;
                pa[it] = *(const float4*)(A + (size_t)(m0 + r) * K + k0 + gc4);
                pb[it] = *(const float4*)(W + (size_t)(n0 + r) * K + k0 + gc4);
            }
        }

#pragma unroll
        for (int ks = 0; ks < 2; ++ks) {
            const int k0 = ks * 8;
            uint32_t af[4][4], bf[4][2];
#pragma unroll
            for (int mt = 0; mt < 4; ++mt) {
                int rb = wm0 + mt * 16 + qr;
                af[mt][0] = As[cur][rb    ][k0 + ql];
                af[mt][1] = As[cur][rb + 8][k0 + ql];
                af[mt][2] = As[cur][rb    ][k0 + ql + 4];
                af[mt][3] = As[cur][rb + 8][k0 + ql + 4];
            }
#pragma unroll
            for (int nt = 0; nt < 4; ++nt) {
                int nb = wn0 + nt * 8 + qr;
                bf[nt][0] = Bs[cur][nb][k0 + ql];
                bf[nt][1] = Bs[cur][nb][k0 + ql + 4];
            }
#pragma unroll
            for (int mt = 0; mt < 4; ++mt)
#pragma unroll
                for (int nt = 0; nt < 4; ++nt)
                    mma_tf32(acc[mt][nt], af[mt], bf[nt]);
        }

        if (kt + 1 < NT) {
            const int nxt = cur ^ 1;
#pragma unroll
            for (int it = 0; it < 2; ++it) {
                int r = grow + it * 64;
                As[nxt][r][gc4 + 0] = f2tf32(pa[it].x);
                As[nxt][r][gc4 + 1] = f2tf32(pa[it].y);
                As[nxt][r][gc4 + 2] = f2tf32(pa[it].z);
                As[nxt][r][gc4 + 3] = f2tf32(pa[it].w);
                Bs[nxt][r][gc4 + 0] = f2tf32(pb[it].x);
                Bs[nxt][r][gc4 + 1] = f2tf32(pb[it].y);
                Bs[nxt][r][gc4 + 2] = f2tf32(pb[it].z);
                Bs[nxt][r][gc4 + 3] = f2tf32(pb[it].w);
            }
            __syncthreads();
        }
    }

#pragma unroll
    for (int mt = 0; mt < 4; ++mt) {
#pragma unroll
        for (int nt = 0; nt < 4; ++nt) {
#pragma unroll
            for (int half = 0; half < 2; ++half) {
                int m = m0 + wm0 + mt * 16 + qr + half * 8;
                int n = n0 + wn0 + nt * 8 + ql * 2;
                float* p;
                if (MODE == 0) {
                    p = C + (size_t)m * N + n;
                } else {
                    int b  = m >> 11;
                    int s  = m & (S_ - 1);
                    int h  = n >> 6;
                    int dk = n & 63;
                    p = C + ((size_t)((b * H_ + h) * S_ + s)) * DK_ + dk;
                }
                *(float2*)p = make_float2(acc[mt][nt][half * 2],
                                          acc[mt][nt][half * 2 + 1]);
            }
        }
    }
}

__global__ __launch_bounds__(256)
void gemm_qkv(const float* __restrict__ q, const float* __restrict__ k,
              const float* __restrict__ v,
              const float* __restrict__ Wq, const float* __restrict__ Wk,
              const float* __restrict__ Wv,
              float* __restrict__ Qo, float* __restrict__ Ko,
              float* __restrict__ Vo) {
    const float* A = (blockIdx.z == 0) ? q  : (blockIdx.z == 1) ? k  : v;
    const float* W = (blockIdx.z == 0) ? Wq : (blockIdx.z == 1) ? Wk : Wv;
    float*       C = (blockIdx.z == 0) ? Qo : (blockIdx.z == 1) ? Ko : Vo;
    gemm_core<1>(A, W, C, M_, D_, D_, blockIdx.x, blockIdx.y);
}

__global__ __launch_bounds__(256)
void gemm_out(const float* __restrict__ A, const float* __restrict__ W,
              float* __restrict__ C) {
    gemm_core<0>(A, W, C, M_, D_, D_, blockIdx.x, blockIdx.y);
}

// ============================================================================
// Flash attention with TF32 tensor cores. Causal.
// 64 q-rows per block, 64-col kv tiles, 128 threads (4 warps).
// Warp w owns q-rows [w*16, w*16+16): QK^T and PV as m16n8k8 MMAs.
// Softmax fully in-register per warp (+2 shuffles). P staged via K's smem
// buffer (tf32). Q/K/P stride 68, V stride 72 -> conflict-free frag loads.
// ============================================================================
#define ASTR_QKP 68
#define ASTR_V   72
#define ASM_Q  (64 * ASTR_QKP)
#define ASM_KP (64 * ASTR_QKP)
#define ASM_V  (64 * ASTR_V)
#define ATT_SMEM ((ASM_Q + ASM_KP + ASM_V) * (int)sizeof(uint32_t))

__global__ __launch_bounds__(128)
void attn_mma(const float* __restrict__ Q, const float* __restrict__ K,
              const float* __restrict__ V, float* __restrict__ Out) {
    extern __shared__ uint32_t smw[];
    uint32_t* sQ  = smw;                    // [64][68] tf32
    uint32_t* sKP = smw + ASM_Q;            // K tile, then P tile [64][68]
    uint32_t* sV  = smw + ASM_Q + ASM_KP;   // [64][72] tf32

    const int qt  = blockIdx.x;             // 0..31
    const int bh  = blockIdx.y;             // 0..63
    const int tid = threadIdx.x;
    const int wid = tid >> 5;
    const int lane = tid & 31;
    const int qr = lane >> 2;               // 0..7
    const int ql = lane & 3;                // 0..3
    const int wm = wid * 16;                // warp q-row origin

    // Load Q tile once (tf32)
    {
        const float* Qg = Q + ((size_t)bh * S_ + qt * 64) * DK_;
#pragma unroll
        for (int it = 0; it < 8; ++it) {
            int f = tid + it * 128;          // 0..1023 float4 ids
            int row = f >> 4;
            int c4  = (f & 15) << 2;
            float4 v = *(const float4*)(Qg + row * 64 + c4);
            uint32_t* d = &sQ[row * ASTR_QKP + c4];
            d[0] = f2tf32(v.x); d[1] = f2tf32(v.y);
            d[2] = f2tf32(v.z); d[3] = f2tf32(v.w);
        }
    }

    float mrow0 = -1e30f, mrow1 = -1e30f, lrow0 = 0.f, lrow1 = 0.f;
    float o[8][4];
#pragma unroll
    for (int nt = 0; nt < 8; ++nt)
#pragma unroll
        for (int e = 0; e < 4; ++e) o[nt][e] = 0.f;

    for (int t = 0; t <= qt; ++t) {
        __syncthreads();  // prev PV readers done (t=0: Q store visibility)

        // Stage K (->sKP) and V (->sV), tf32
        const float* Kg = K + ((size_t)bh * S_ + t * 64) * DK_;
        const float* Vg = V + ((size_t)bh * S_ + t * 64) * DK_;
#pragma unroll
        for (int it = 0; it < 8; ++it) {
            int f = tid + it * 128;
            int row = f >> 4;
            int c4  = (f & 15) << 2;
            float4 kv4 = *(const float4*)(Kg + row * 64 + c4);
            uint32_t* dk_ = &sKP[row * ASTR_QKP + c4];
            dk_[0] = f2tf32(kv4.x); dk_[1] = f2tf32(kv4.y);
            dk_[2] = f2tf32(kv4.z); dk_[3] = f2tf32(kv4.w);
            float4 vv4 = *(const float4*)(Vg + row * 64 + c4);
            uint32_t* dv_ = &sV[row * ASTR_V + c4];
            dv_[0] = f2tf32(vv4.x); dv_[1] = f2tf32(vv4.y);
            dv_[2] = f2tf32(vv4.z); dv_[3] = f2tf32(vv4.w);
        }
        __syncthreads();

        // ---- QK^T: 16x64 per warp ----
        float sc[8][4];
#pragma unroll
        for (int nt = 0; nt < 8; ++nt)
#pragma unroll
            for (int e = 0; e < 4; ++e) sc[nt][e] = 0.f;

#pragma unroll
        for (int k0 = 0; k0 < 64; k0 += 8) {
            uint32_t a[4];
            a[0] = sQ[(wm + qr    ) * ASTR_QKP + k0 + ql];
            a[1] = sQ[(wm + qr + 8) * ASTR_QKP + k0 + ql];
            a[2] = sQ[(wm + qr    ) * ASTR_QKP + k0 + ql + 4];
            a[3] = sQ[(wm + qr + 8) * ASTR_QKP + k0 + ql + 4];
#pragma unroll
            for (int nt = 0; nt < 8; ++nt) {
                uint32_t b[2];
                b[0] = sKP[(nt * 8 + qr) * ASTR_QKP + k0 + ql];
                b[1] = sKP[(nt * 8 + qr) * ASTR_QKP + k0 + ql + 4];
                mma_tf32(sc[nt], a, b);
            }
        }
        __syncthreads();  // all warps done reading K before P overwrites sKP

        // ---- scale + causal mask + online softmax ----
        const int r0l = wm + qr, r1l = wm + qr + 8;
        float tm0 = -1e30f, tm1 = -1e30f;
#pragma unroll
        for (int nt = 0; nt < 8; ++nt) {
            const int c0 = nt * 8 + 2 * ql, c1 = c0 + 1;
#pragma unroll
            for (int e = 0; e < 4; ++e) sc[nt][e] *= 0.125f;
            if (t == qt) {
                if (c0 > r0l) sc[nt][0] = -1e9f;
                if (c1 > r0l) sc[nt][1] = -1e9f;
                if (c0 > r1l) sc[nt][2] = -1e9f;
                if (c1 > r1l) sc[nt][3] = -1e9f;
            }
            tm0 = fmaxf(tm0, fmaxf(sc[nt][0], sc[nt][1]));
            tm1 = fmaxf(tm1, fmaxf(sc[nt][2], sc[nt][3]));
        }
        tm0 = fmaxf(tm0, __shfl_xor_sync(0xffffffffu, tm0, 1));
        tm0 = fmaxf(tm0, __shfl_xor_sync(0xffffffffu, tm0, 2));
        tm1 = fmaxf(tm1, __shfl_xor_sync(0xffffffffu, tm1, 1));
        tm1 = fmaxf(tm1, __shfl_xor_sync(0xffffffffu, tm1, 2));

        const float nm0 = fmaxf(mrow0, tm0);
        const float nm1 = fmaxf(mrow1, tm1);
        const float al0 = __expf(mrow0 - nm0);
        const float al1 = __expf(mrow1 - nm1);
        float sum0 = 0.f, sum1 = 0.f;
#pragma unroll
        for (int nt = 0; nt < 8; ++nt) {
            sc[nt][0] = __expf(sc[nt][0] - nm0);
            sc[nt][1] = __expf(sc[nt][1] - nm0);
            sc[nt][2] = __expf(sc[nt][2] - nm1);
            sc[nt][3] = __expf(sc[nt][3] - nm1);
            sum0 += sc[nt][0] + sc[nt][1];
            sum1 += sc[nt][2] + sc[nt][3];
        }
        sum0 += __shfl_xor_sync(0xffffffffu, sum0, 1);
        sum0 += __shfl_xor_sync(0xffffffffu, sum0, 2);
        sum1 += __shfl_xor_sync(0xffffffffu, sum1, 1);
        sum1 += __shfl_xor_sync(0xffffffffu, sum1, 2);

        lrow0 = lrow0 * al0 + sum0;
        lrow1 = lrow1 * al1 + sum1;
        mrow0 = nm0; mrow1 = nm1;

#pragma unroll
        for (int nt = 0; nt < 8; ++nt) {
            o[nt][0] *= al0; o[nt][1] *= al0;
            o[nt][2] *= al1; o[nt][3] *= al1;
        }

        // Store P (tf32) into sKP — warp-private rows
#pragma unroll
        for (int nt = 0; nt < 8; ++nt) {
            const int base0 = (wm + qr) * ASTR_QKP + nt * 8 + 2 * ql;
            sKP[base0]     = f2tf32(sc[nt][0]);
            sKP[base0 + 1] = f2tf32(sc[nt][1]);
            const int base1 = base0 + 8 * ASTR_QKP;
            sKP[base1]     = f2tf32(sc[nt][2]);
            sKP[base1 + 1] = f2tf32(sc[nt][3]);
        }
        __syncwarp();

        // ---- PV: O += P @ V ----
#pragma unroll
        for (int k0 = 0; k0 < 64; k0 += 8) {
            uint32_t a[4];
            a[0] = sKP[(wm + qr    ) * ASTR_QKP + k0 + ql];
            a[1] = sKP[(wm + qr + 8) * ASTR_QKP + k0 + ql];
            a[2] = sKP[(wm + qr    ) * ASTR_QKP + k0 + ql + 4];
            a[3] = sKP[(wm + qr + 8) * ASTR_QKP + k0 + ql + 4];
#pragma unroll
            for (int nt = 0; nt < 8; ++nt) {
                uint32_t b[2];
                b[0] = sV[(k0 + ql    ) * ASTR_V + nt * 8 + qr];
                b[1] = sV[(k0 + ql + 4) * ASTR_V + nt * 8 + qr];
                mma_tf32(o[nt], a, b);
            }
        }
    }

    // Epilogue -> [B,S,D]
    const float i0 = 1.f / lrow0, i1 = 1.f / lrow1;
    const int b = bh >> 4, h = bh & 15;
    const int s0 = qt * 64 + wm + qr, s1 = s0 + 8;
#pragma unroll
    for (int nt = 0; nt < 8; ++nt) {
        const int dk = nt * 8 + 2 * ql;
        float* p0 = Out + ((size_t)(b * S_ + s0)) * D_ + h * DK_ + dk;
        *(float2*)p0 = make_float2(o[nt][0] * i0, o[nt][1] * i0);
        float* p1 = Out + ((size_t)(b * S_ + s1)) * D_ + h * DK_ + dk;
        *(float2*)p1 = make_float2(o[nt][2] * i1, o[nt][3] * i1);
    }
}

// ============================================================================
// Launch
// ============================================================================
extern "C" void kernel_launch(void* const* d_in, const int* in_sizes, int n_in,
                              void* d_out, int out_size) {
    const float* q  = (const float*)d_in[0];
    const float* k  = (const float*)d_in[1];
    const float* v  = (const float*)d_in[2];
    // d_in[3] = mask (causal, known statically) — unused
    const float* Wq = (const float*)d_in[4];
    const float* Wk = (const float*)d_in[5];
    const float* Wv = (const float*)d_in[6];
    const float* Wo = (const float*)d_in[7];
    float* out = (float*)d_out;

    float *pQ, *pK, *pV, *pA;
    cudaGetSymbolAddress((void**)&pQ, g_Q);
    cudaGetSymbolAddress((void**)&pK, g_K);
    cudaGetSymbolAddress((void**)&pV, g_V);
    cudaGetSymbolAddress((void**)&pA, g_A);

    dim3 qkv_grid(D_ / BN, M_ / BM, 3);   // (8, 64, 3)
    gemm_qkv<<<qkv_grid, 256>>>(q, k, v, Wq, Wk, Wv, pQ, pK, pV);

    cudaFuncSetAttribute(attn_mma,
                         cudaFuncAttributeMaxDynamicSharedMemorySize, ATT_SMEM);
    attn_mma<<<dim3(S_ / 64, B_ * H_), 128, ATT_SMEM>>>(pQ, pK, pV, pA);

    dim3 ogrid(D_ / BN, M_ / BM);         // (8, 64)
    gemm_out<<<ogrid, 256>>>(pA, Wo, out);
}

// round 7
// speedup vs baseline: 4.5829x; 1.0268x over previous
#include <cuda_runtime.h>
#include <cstdint>

// Problem constants
#define B_  4
#define S_  2048
#define D_  1024
#define H_  16
#define DK_ 64
#define M_  (B_*S_)   // 8192

// Scratch (device globals — no allocations allowed)
__device__ float g_Q[(size_t)B_*H_*S_*DK_];
__device__ float g_K[(size_t)B_*H_*S_*DK_];
__device__ float g_V[(size_t)B_*H_*S_*DK_];
__device__ float g_A[(size_t)B_*S_*D_];

__device__ __forceinline__ uint32_t f2tf32(float f) {
    uint32_t u;
    asm("cvt.rna.tf32.f32 %0, %1;" : "=r"(u) : "f"(f));
    return u;
}

__device__ __forceinline__ void mma_tf32(float d[4], const uint32_t a[4],
                                         const uint32_t b[2]) {
    asm volatile(
        "mma.sync.aligned.m16n8k8.row.col.f32.tf32.tf32.f32 "
        "{%0,%1,%2,%3}, {%4,%5,%6,%7}, {%8,%9}, {%0,%1,%2,%3};\n"
        : "+f"(d[0]), "+f"(d[1]), "+f"(d[2]), "+f"(d[3])
        : "r"(a[0]), "r"(a[1]), "r"(a[2]), "r"(a[3]),
          "r"(b[0]), "r"(b[1]));
}

// ============================================================================
// TF32 tensor-core GEMM with FRAGMENT-MAJOR smem: C = A @ W^T.
// A:[M,K] rm, W:[N,K] rm. Block 128x128, BK=16, 256 thr, warp tile 64x32.
// Staging writes each tf32 element directly at its mma-fragment position:
//   element (r,k) in the 128x16 tile:
//     A: reg = (k%8>=4)*2 + (r%16>=8), lane = (r%8)*4 + k%4
//        idx = ((r/16)*2 + k/8)*132 + lane*4 + reg          -> LDS.128 consumer
//     W: reg = (k%8>=4),               lane = (n%8)*4 + k%4
//        idx = ((n/8)*2 + k/8)*66 + lane*2 + reg            -> LDS.64 consumer
// MODE 0: C row-major [M,N]. MODE 1: split-heads epilogue.
// ============================================================================
#define BM 128
#define BN 128
#define AF_SB 132   // floats per (mrow16, ks) sub-block (128 + 4 pad)
#define BF_SB 66    // floats per (nrow8,  ks) sub-block (64 + 2 pad)
#define AF_SZ (16 * AF_SB)   // 8 mrow * 2 ks
#define BF_SZ (32 * BF_SB)   // 16 nrow * 2 ks

template<int MODE>
__device__ __forceinline__
void gemm_core(const float* __restrict__ A, const float* __restrict__ W,
               float* __restrict__ C, int M, int N, int K,
               int bx, int by) {
    __shared__ uint32_t AF[2][AF_SZ];
    __shared__ uint32_t BF[2][BF_SZ];

    const int m0 = by * BM;
    const int n0 = bx * BN;
    const int tid = threadIdx.x;
    const int wid = tid >> 5;
    const int lane = tid & 31;

    const int wm0 = (wid & 1) * 64;   // warp m-origin
    const int wn0 = (wid >> 1) * 32;  // warp n-origin

    // Staging coords: thread covers rows grow, grow+64; k-cols c40..c40+3
    const int grow = tid >> 2;             // 0..63
    const int c40  = (tid & 3) << 2;       // 0,4,8,12
    const int ks_s = c40 >> 3;             // 0/1
    const int rA   = (c40 >> 2) & 1;       // high-k half -> +2 in A reg

    float acc[4][4][4];
#pragma unroll
    for (int mt = 0; mt < 4; ++mt)
#pragma unroll
        for (int nt = 0; nt < 4; ++nt)
#pragma unroll
            for (int i = 0; i < 4; ++i) acc[mt][nt][i] = 0.f;

    const int NT = K / 16;

    // Fragment-position store of one float4 (A row r, cols c40..c40+3)
    auto stA = [&](int buf, int r, float4 v) {
        const int base = ((r >> 4) * 2 + ks_s) * AF_SB
                       + ((r & 7) * 4) * 4 + rA * 2 + ((r >> 3) & 1);
        AF[buf][base     ] = f2tf32(v.x);
        AF[buf][base +  4] = f2tf32(v.y);
        AF[buf][base +  8] = f2tf32(v.z);
        AF[buf][base + 12] = f2tf32(v.w);
    };
    auto stB = [&](int buf, int r, float4 v) {
        const int base = ((r >> 3) * 2 + ks_s) * BF_SB
                       + ((r & 7) * 4) * 2 + rA;
        BF[buf][base    ] = f2tf32(v.x);
        BF[buf][base + 2] = f2tf32(v.y);
        BF[buf][base + 4] = f2tf32(v.z);
        BF[buf][base + 6] = f2tf32(v.w);
    };

    // Prologue: stage tile 0
#pragma unroll
    for (int it = 0; it < 2; ++it) {
        int r = grow + it * 64;
        stA(0, r, *(const float4*)(A + (size_t)(m0 + r) * K + c40));
        stB(0, r, *(const float4*)(W + (size_t)(n0 + r) * K + c40));
    }
    __syncthreads();

    for (int kt = 0; kt < NT; ++kt) {
        const int cur = kt & 1;

        // Prefetch next tile gmem -> regs
        float4 pa[2], pb[2];
        if (kt + 1 < NT) {
            const int k0 = (kt + 1) * 16;
#pragma unroll
            for (int it = 0; it < 2; ++it) {
                int r = grow + it * 64;
                pa[it] = *(const float4*)(A + (size_t)(m0 + r) * K + k0 + c40);
                pb[it] = *(const float4*)(W + (size_t)(n0 + r) * K + k0 + c40);
            }
        }

        // Compute: 2 k-steps of 8, wide fragment loads
#pragma unroll
        for (int ks = 0; ks < 2; ++ks) {
            uint4 av[4];
            uint2 bv[4];
#pragma unroll
            for (int mt = 0; mt < 4; ++mt)
                av[mt] = *(const uint4*)&AF[cur][(((wm0 >> 4) + mt) * 2 + ks) * AF_SB + lane * 4];
#pragma unroll
            for (int nt = 0; nt < 4; ++nt)
                bv[nt] = *(const uint2*)&BF[cur][(((wn0 >> 3) + nt) * 2 + ks) * BF_SB + lane * 2];
#pragma unroll
            for (int mt = 0; mt < 4; ++mt)
#pragma unroll
                for (int nt = 0; nt < 4; ++nt)
                    mma_tf32(acc[mt][nt], (const uint32_t*)&av[mt],
                             (const uint32_t*)&bv[nt]);
        }

        // Store prefetched tile to the other buffer
        if (kt + 1 < NT) {
            const int nxt = cur ^ 1;
#pragma unroll
            for (int it = 0; it < 2; ++it) {
                int r = grow + it * 64;
                stA(nxt, r, pa[it]);
                stB(nxt, r, pb[it]);
            }
            __syncthreads();
        }
    }

    // Epilogue (c-frag: c0,c1 @(row,col..col+1); c2,c3 @(row+8,...))
    const int qr = lane >> 2;
    const int ql = lane & 3;
#pragma unroll
    for (int mt = 0; mt < 4; ++mt) {
#pragma unroll
        for (int nt = 0; nt < 4; ++nt) {
#pragma unroll
            for (int half = 0; half < 2; ++half) {
                int m = m0 + wm0 + mt * 16 + qr + half * 8;
                int n = n0 + wn0 + nt * 8 + ql * 2;
                float* p;
                if (MODE == 0) {
                    p = C + (size_t)m * N + n;
                } else {
                    int b  = m >> 11;
                    int s  = m & (S_ - 1);
                    int h  = n >> 6;
                    int dk = n & 63;
                    p = C + ((size_t)((b * H_ + h) * S_ + s)) * DK_ + dk;
                }
                *(float2*)p = make_float2(acc[mt][nt][half * 2],
                                          acc[mt][nt][half * 2 + 1]);
            }
        }
    }
}

__global__ __launch_bounds__(256, 2)
void gemm_qkv(const float* __restrict__ q, const float* __restrict__ k,
              const float* __restrict__ v,
              const float* __restrict__ Wq, const float* __restrict__ Wk,
              const float* __restrict__ Wv,
              float* __restrict__ Qo, float* __restrict__ Ko,
              float* __restrict__ Vo) {
    const float* A = (blockIdx.z == 0) ? q  : (blockIdx.z == 1) ? k  : v;
    const float* W = (blockIdx.z == 0) ? Wq : (blockIdx.z == 1) ? Wk : Wv;
    float*       C = (blockIdx.z == 0) ? Qo : (blockIdx.z == 1) ? Ko : Vo;
    gemm_core<1>(A, W, C, M_, D_, D_, blockIdx.x, blockIdx.y);
}

__global__ __launch_bounds__(256, 2)
void gemm_out(const float* __restrict__ A, const float* __restrict__ W,
              float* __restrict__ C) {
    gemm_core<0>(A, W, C, M_, D_, D_, blockIdx.x, blockIdx.y);
}

// ============================================================================
// Flash attention with TF32 tensor cores (unchanged from passing R5 kernel).
// ============================================================================
#define ASTR_QKP 68
#define ASTR_V   72
#define ASM_Q  (64 * ASTR_QKP)
#define ASM_KP (64 * ASTR_QKP)
#define ASM_V  (64 * ASTR_V)
#define ATT_SMEM ((ASM_Q + ASM_KP + ASM_V) * (int)sizeof(uint32_t))

__global__ __launch_bounds__(128)
void attn_mma(const float* __restrict__ Q, const float* __restrict__ K,
              const float* __restrict__ V, float* __restrict__ Out) {
    extern __shared__ uint32_t smw[];
    uint32_t* sQ  = smw;
    uint32_t* sKP = smw + ASM_Q;
    uint32_t* sV  = smw + ASM_Q + ASM_KP;

    const int qt  = blockIdx.x;
    const int bh  = blockIdx.y;
    const int tid = threadIdx.x;
    const int wid = tid >> 5;
    const int lane = tid & 31;
    const int qr = lane >> 2;
    const int ql = lane & 3;
    const int wm = wid * 16;

    {
        const float* Qg = Q + ((size_t)bh * S_ + qt * 64) * DK_;
#pragma unroll
        for (int it = 0; it < 8; ++it) {
            int f = tid + it * 128;
            int row = f >> 4;
            int c4  = (f & 15) << 2;
            float4 v = *(const float4*)(Qg + row * 64 + c4);
            uint32_t* d = &sQ[row * ASTR_QKP + c4];
            d[0] = f2tf32(v.x); d[1] = f2tf32(v.y);
            d[2] = f2tf32(v.z); d[3] = f2tf32(v.w);
        }
    }

    float mrow0 = -1e30f, mrow1 = -1e30f, lrow0 = 0.f, lrow1 = 0.f;
    float o[8][4];
#pragma unroll
    for (int nt = 0; nt < 8; ++nt)
#pragma unroll
        for (int e = 0; e < 4; ++e) o[nt][e] = 0.f;

    for (int t = 0; t <= qt; ++t) {
        __syncthreads();
        const float* Kg = K + ((size_t)bh * S_ + t * 64) * DK_;
        const float* Vg = V + ((size_t)bh * S_ + t * 64) * DK_;
#pragma unroll
        for (int it = 0; it < 8; ++it) {
            int f = tid + it * 128;
            int row = f >> 4;
            int c4  = (f & 15) << 2;
            float4 kv4 = *(const float4*)(Kg + row * 64 + c4);
            uint32_t* dk_ = &sKP[row * ASTR_QKP + c4];
            dk_[0] = f2tf32(kv4.x); dk_[1] = f2tf32(kv4.y);
            dk_[2] = f2tf32(kv4.z); dk_[3] = f2tf32(kv4.w);
            float4 vv4 = *(const float4*)(Vg + row * 64 + c4);
            uint32_t* dv_ = &sV[row * ASTR_V + c4];
            dv_[0] = f2tf32(vv4.x); dv_[1] = f2tf32(vv4.y);
            dv_[2] = f2tf32(vv4.z); dv_[3] = f2tf32(vv4.w);
        }
        __syncthreads();

        float sc[8][4];
#pragma unroll
        for (int nt = 0; nt < 8; ++nt)
#pragma unroll
            for (int e = 0; e < 4; ++e) sc[nt][e] = 0.f;

#pragma unroll
        for (int k0 = 0; k0 < 64; k0 += 8) {
            uint32_t a[4];
            a[0] = sQ[(wm + qr    ) * ASTR_QKP + k0 + ql];
            a[1] = sQ[(wm + qr + 8) * ASTR_QKP + k0 + ql];
            a[2] = sQ[(wm + qr    ) * ASTR_QKP + k0 + ql + 4];
            a[3] = sQ[(wm + qr + 8) * ASTR_QKP + k0 + ql + 4];
#pragma unroll
            for (int nt = 0; nt < 8; ++nt) {
                uint32_t b[2];
                b[0] = sKP[(nt * 8 + qr) * ASTR_QKP + k0 + ql];
                b[1] = sKP[(nt * 8 + qr) * ASTR_QKP + k0 + ql + 4];
                mma_tf32(sc[nt], a, b);
            }
        }
        __syncthreads();

        const int r0l = wm + qr, r1l = wm + qr + 8;
        float tm0 = -1e30f, tm1 = -1e30f;
#pragma unroll
        for (int nt = 0; nt < 8; ++nt) {
            const int c0 = nt * 8 + 2 * ql, c1 = c0 + 1;
#pragma unroll
            for (int e = 0; e < 4; ++e) sc[nt][e] *= 0.125f;
            if (t == qt) {
                if (c0 > r0l) sc[nt][0] = -1e9f;
                if (c1 > r0l) sc[nt][1] = -1e9f;
                if (c0 > r1l) sc[nt][2] = -1e9f;
                if (c1 > r1l) sc[nt][3] = -1e9f;
            }
            tm0 = fmaxf(tm0, fmaxf(sc[nt][0], sc[nt][1]));
            tm1 = fmaxf(tm1, fmaxf(sc[nt][2], sc[nt][3]));
        }
        tm0 = fmaxf(tm0, __shfl_xor_sync(0xffffffffu, tm0, 1));
        tm0 = fmaxf(tm0, __shfl_xor_sync(0xffffffffu, tm0, 2));
        tm1 = fmaxf(tm1, __shfl_xor_sync(0xffffffffu, tm1, 1));
        tm1 = fmaxf(tm1, __shfl_xor_sync(0xffffffffu, tm1, 2));

        const float nm0 = fmaxf(mrow0, tm0);
        const float nm1 = fmaxf(mrow1, tm1);
        const float al0 = __expf(mrow0 - nm0);
        const float al1 = __expf(mrow1 - nm1);
        float sum0 = 0.f, sum1 = 0.f;
#pragma unroll
        for (int nt = 0; nt < 8; ++nt) {
            sc[nt][0] = __expf(sc[nt][0] - nm0);
            sc[nt][1] = __expf(sc[nt][1] - nm0);
            sc[nt][2] = __expf(sc[nt][2] - nm1);
            sc[nt][3] = __expf(sc[nt][3] - nm1);
            sum0 += sc[nt][0] + sc[nt][1];
            sum1 += sc[nt][2] + sc[nt][3];
        }
        sum0 += __shfl_xor_sync(0xffffffffu, sum0, 1);
        sum0 += __shfl_xor_sync(0xffffffffu, sum0, 2);
        sum1 += __shfl_xor_sync(0xffffffffu, sum1, 1);
        sum1 += __shfl_xor_sync(0xffffffffu, sum1, 2);

        lrow0 = lrow0 * al0 + sum0;
        lrow1 = lrow1 * al1 + sum1;
        mrow0 = nm0; mrow1 = nm1;

#pragma unroll
        for (int nt = 0; nt < 8; ++nt) {
            o[nt][0] *= al0; o[nt][1] *= al0;
            o[nt][2] *= al1; o[nt][3] *= al1;
        }

#pragma unroll
        for (int nt = 0; nt < 8; ++nt) {
            const int base0 = (wm + qr) * ASTR_QKP + nt * 8 + 2 * ql;
            sKP[base0]     = f2tf32(sc[nt][0]);
            sKP[base0 + 1] = f2tf32(sc[nt][1]);
            const int base1 = base0 + 8 * ASTR_QKP;
            sKP[base1]     = f2tf32(sc[nt][2]);
            sKP[base1 + 1] = f2tf32(sc[nt][3]);
        }
        __syncwarp();

#pragma unroll
        for (int k0 = 0; k0 < 64; k0 += 8) {
            uint32_t a[4];
            a[0] = sKP[(wm + qr    ) * ASTR_QKP + k0 + ql];
            a[1] = sKP[(wm + qr + 8) * ASTR_QKP + k0 + ql];
            a[2] = sKP[(wm + qr    ) * ASTR_QKP + k0 + ql + 4];
            a[3] = sKP[(wm + qr + 8) * ASTR_QKP + k0 + ql + 4];
#pragma unroll
            for (int nt = 0; nt < 8; ++nt) {
                uint32_t b[2];
                b[0] = sV[(k0 + ql    ) * ASTR_V + nt * 8 + qr];
                b[1] = sV[(k0 + ql + 4) * ASTR_V + nt * 8 + qr];
                mma_tf32(o[nt], a, b);
            }
        }
    }

    const float i0 = 1.f / lrow0, i1 = 1.f / lrow1;
    const int b = bh >> 4, h = bh & 15;
    const int s0 = qt * 64 + wm + qr, s1 = s0 + 8;
#pragma unroll
    for (int nt = 0; nt < 8; ++nt) {
        const int dk = nt * 8 + 2 * ql;
        float* p0 = Out + ((size_t)(b * S_ + s0)) * D_ + h * DK_ + dk;
        *(float2*)p0 = make_float2(o[nt][0] * i0, o[nt][1] * i0);
        float* p1 = Out + ((size_t)(b * S_ + s1)) * D_ + h * DK_ + dk;
        *(float2*)p1 = make_float2(o[nt][2] * i1, o[nt][3] * i1);
    }
}

// ============================================================================
// Launch
// ============================================================================
extern "C" void kernel_launch(void* const* d_in, const int* in_sizes, int n_in,
                              void* d_out, int out_size) {
    const float* q  = (const float*)d_in[0];
    const float* k  = (const float*)d_in[1];
    const float* v  = (const float*)d_in[2];
    // d_in[3] = mask (causal, known statically) — unused
    const float* Wq = (const float*)d_in[4];
    const float* Wk = (const float*)d_in[5];
    const float* Wv = (const float*)d_in[6];
    const float* Wo = (const float*)d_in[7];
    float* out = (float*)d_out;

    float *pQ, *pK, *pV, *pA;
    cudaGetSymbolAddress((void**)&pQ, g_Q);
    cudaGetSymbolAddress((void**)&pK, g_K);
    cudaGetSymbolAddress((void**)&pV, g_V);
    cudaGetSymbolAddress((void**)&pA, g_A);

    dim3 qkv_grid(D_ / BN, M_ / BM, 3);   // (8, 64, 3)
    gemm_qkv<<<qkv_grid, 256>>>(q, k, v, Wq, Wk, Wv, pQ, pK, pV);

    cudaFuncSetAttribute(attn_mma,
                         cudaFuncAttributeMaxDynamicSharedMemorySize, ATT_SMEM);
    attn_mma<<<dim3(S_ / 64, B_ * H_), 128, ATT_SMEM>>>(pQ, pK, pV, pA);

    dim3 ogrid(D_ / BN, M_ / BM);         // (8, 64)
    gemm_out<<<ogrid, 256>>>(pA, Wo, out);
}

// round 9
// speedup vs baseline: 4.8363x; 1.0553x over previous
#include <cuda_runtime.h>
#include <cstdint>

// Problem constants
#define B_  4
#define S_  2048
#define D_  1024
#define H_  16
#define DK_ 64
#define M_  (B_*S_)   // 8192

// Scratch (device globals — no allocations allowed)
__device__ float g_Q[(size_t)B_*H_*S_*DK_];
__device__ float g_K[(size_t)B_*H_*S_*DK_];
__device__ float g_V[(size_t)B_*H_*S_*DK_];
__device__ float g_A[(size_t)B_*S_*D_];

__device__ __forceinline__ uint32_t f2tf32(float f) {
    uint32_t u;
    asm("cvt.rna.tf32.f32 %0, %1;" : "=r"(u) : "f"(f));
    return u;
}

__device__ __forceinline__ void mma_tf32(float d[4], const uint32_t a[4],
                                         const uint32_t b[2]) {
    asm volatile(
        "mma.sync.aligned.m16n8k8.row.col.f32.tf32.tf32.f32 "
        "{%0,%1,%2,%3}, {%4,%5,%6,%7}, {%8,%9}, {%0,%1,%2,%3};\n"
        : "+f"(d[0]), "+f"(d[1]), "+f"(d[2]), "+f"(d[3])
        : "r"(a[0]), "r"(a[1]), "r"(a[2]), "r"(a[3]),
          "r"(b[0]), "r"(b[1]));
}

// ============================================================================
// TF32 tensor-core GEMM, FRAGMENT-MAJOR smem (DYNAMIC): C = A @ W^T.
// A:[M,K] rm, W:[N,K] rm. Block 128x256, BK=16, 256 thr, 8 warps of 64x64.
// Fragment positions (verified in R7):
//   A: sub-block (r/16, k/8), idx = lane*4 + reg, reg=(k%8>=4)*2+(r%16>=8),
//      lane=(r%8)*4+k%4, sub stride 132                   -> LDS.128 consumer
//   W: sub-block (n/8, k/8),  idx = lane*2 + reg, reg=(k%8>=4),
//      lane=(n%8)*4+k%4, sub stride 66                    -> LDS.64 consumer
// MODE 0: C row-major [M,N]. MODE 1: split-heads epilogue.
// ============================================================================
#define BM 128
#define BN 256
#define AF_SB 132
#define BF_SB 66
#define AF_SZ (16 * AF_SB)    // per buffer: 8 mrow-blocks * 2 ks
#define BF_SZ (64 * BF_SB)    // per buffer: 32 nrow-blocks * 2 ks
#define GEMM_SMEM ((2 * AF_SZ + 2 * BF_SZ) * (int)sizeof(uint32_t))  // 50688 B

template<int MODE>
__device__ __forceinline__
void gemm_core(const float* __restrict__ A, const float* __restrict__ W,
               float* __restrict__ C, int M, int N, int K,
               int bx, int by) {
    extern __shared__ uint32_t dyn[];
    uint32_t* AF = dyn;                 // [2][AF_SZ]
    uint32_t* BF = dyn + 2 * AF_SZ;     // [2][BF_SZ]

    const int m0 = by * BM;
    const int n0 = bx * BN;
    const int tid = threadIdx.x;
    const int wid = tid >> 5;
    const int lane = tid & 31;

    const int wm0 = (wid & 1) * 64;    // warp m-origin (2 slots)
    const int wn0 = (wid >> 1) * 64;   // warp n-origin (4 slots)

    // Staging coords: thread covers rows grow(+64/128/192); k-cols c40..c40+3
    const int grow = tid >> 2;             // 0..63
    const int c40  = (tid & 3) << 2;       // 0,4,8,12
    const int ks_s = c40 >> 3;             // 0/1
    const int rA   = (c40 >> 2) & 1;       // high-k half of a k-step

    float acc[4][8][4];
#pragma unroll
    for (int mt = 0; mt < 4; ++mt)
#pragma unroll
        for (int nt = 0; nt < 8; ++nt)
#pragma unroll
            for (int i = 0; i < 4; ++i) acc[mt][nt][i] = 0.f;

    const int NT = K / 16;

    auto stA = [&](int buf, int r, float4 v) {
        const int base = buf * AF_SZ + ((r >> 4) * 2 + ks_s) * AF_SB
                       + ((r & 7) * 4) * 4 + rA * 2 + ((r >> 3) & 1);
        AF[base     ] = f2tf32(v.x);
        AF[base +  4] = f2tf32(v.y);
        AF[base +  8] = f2tf32(v.z);
        AF[base + 12] = f2tf32(v.w);
    };
    auto stB = [&](int buf, int r, float4 v) {
        const int base = buf * BF_SZ + ((r >> 3) * 2 + ks_s) * BF_SB
                       + ((r & 7) * 4) * 2 + rA;
        BF[base    ] = f2tf32(v.x);
        BF[base + 2] = f2tf32(v.y);
        BF[base + 4] = f2tf32(v.z);
        BF[base + 6] = f2tf32(v.w);
    };

    // Prologue: stage tile 0
#pragma unroll
    for (int it = 0; it < 2; ++it) {
        int r = grow + it * 64;
        stA(0, r, *(const float4*)(A + (size_t)(m0 + r) * K + c40));
    }
#pragma unroll
    for (int it = 0; it < 4; ++it) {
        int r = grow + it * 64;
        stB(0, r, *(const float4*)(W + (size_t)(n0 + r) * K + c40));
    }
    __syncthreads();

    for (int kt = 0; kt < NT; ++kt) {
        const int cur = kt & 1;

        // Prefetch next tile gmem -> regs
        float4 pa[2], pb[4];
        if (kt + 1 < NT) {
            const int k0 = (kt + 1) * 16;
#pragma unroll
            for (int it = 0; it < 2; ++it) {
                int r = grow + it * 64;
                pa[it] = *(const float4*)(A + (size_t)(m0 + r) * K + k0 + c40);
            }
#pragma unroll
            for (int it = 0; it < 4; ++it) {
                int r = grow + it * 64;
                pb[it] = *(const float4*)(W + (size_t)(n0 + r) * K + k0 + c40);
            }
        }

        // Compute: 2 k-steps of 8, wide fragment loads
#pragma unroll
        for (int ks = 0; ks < 2; ++ks) {
            uint4 av[4];
            uint2 bv[8];
#pragma unroll
            for (int mt = 0; mt < 4; ++mt)
                av[mt] = *(const uint4*)&AF[cur * AF_SZ
                        + (((wm0 >> 4) + mt) * 2 + ks) * AF_SB + lane * 4];
#pragma unroll
            for (int nt = 0; nt < 8; ++nt)
                bv[nt] = *(const uint2*)&BF[cur * BF_SZ
                        + (((wn0 >> 3) + nt) * 2 + ks) * BF_SB + lane * 2];
#pragma unroll
            for (int mt = 0; mt < 4; ++mt)
#pragma unroll
                for (int nt = 0; nt < 8; ++nt)
                    mma_tf32(acc[mt][nt], (const uint32_t*)&av[mt],
                             (const uint32_t*)&bv[nt]);
        }

        // Store prefetched tile to the other buffer
        if (kt + 1 < NT) {
            const int nxt = cur ^ 1;
#pragma unroll
            for (int it = 0; it < 2; ++it) {
                int r = grow + it * 64;
                stA(nxt, r, pa[it]);
            }
#pragma unroll
            for (int it = 0; it < 4; ++it) {
                int r = grow + it * 64;
                stB(nxt, r, pb[it]);
            }
            __syncthreads();
        }
    }

    // Epilogue (c-frag: c0,c1 @(row,col..col+1); c2,c3 @(row+8,...))
    const int qr = lane >> 2;
    const int ql = lane & 3;
#pragma unroll
    for (int mt = 0; mt < 4; ++mt) {
#pragma unroll
        for (int nt = 0; nt < 8; ++nt) {
#pragma unroll
            for (int half = 0; half < 2; ++half) {
                int m = m0 + wm0 + mt * 16 + qr + half * 8;
                int n = n0 + wn0 + nt * 8 + ql * 2;
                float* p;
                if (MODE == 0) {
                    p = C + (size_t)m * N + n;
                } else {
                    int b  = m >> 11;
                    int s  = m & (S_ - 1);
                    int h  = n >> 6;
                    int dk = n & 63;
                    p = C + ((size_t)((b * H_ + h) * S_ + s)) * DK_ + dk;
                }
                *(float2*)p = make_float2(acc[mt][nt][half * 2],
                                          acc[mt][nt][half * 2 + 1]);
            }
        }
    }
}

__global__ __launch_bounds__(256, 1)
void gemm_qkv(const float* __restrict__ q, const float* __restrict__ k,
              const float* __restrict__ v,
              const float* __restrict__ Wq, const float* __restrict__ Wk,
              const float* __restrict__ Wv,
              float* __restrict__ Qo, float* __restrict__ Ko,
              float* __restrict__ Vo) {
    const float* A = (blockIdx.z == 0) ? q  : (blockIdx.z == 1) ? k  : v;
    const float* W = (blockIdx.z == 0) ? Wq : (blockIdx.z == 1) ? Wk : Wv;
    float*       C = (blockIdx.z == 0) ? Qo : (blockIdx.z == 1) ? Ko : Vo;
    gemm_core<1>(A, W, C, M_, D_, D_, blockIdx.x, blockIdx.y);
}

__global__ __launch_bounds__(256, 1)
void gemm_out(const float* __restrict__ A, const float* __restrict__ W,
              float* __restrict__ C) {
    gemm_core<0>(A, W, C, M_, D_, D_, blockIdx.x, blockIdx.y);
}

// ============================================================================
// Flash attention with TF32 tensor cores (unchanged from passing R7 kernel).
// ============================================================================
#define ASTR_QKP 68
#define ASTR_V   72
#define ASM_Q  (64 * ASTR_QKP)
#define ASM_KP (64 * ASTR_QKP)
#define ASM_V  (64 * ASTR_V)
#define ATT_SMEM ((ASM_Q + ASM_KP + ASM_V) * (int)sizeof(uint32_t))

__global__ __launch_bounds__(128)
void attn_mma(const float* __restrict__ Q, const float* __restrict__ K,
              const float* __restrict__ V, float* __restrict__ Out) {
    extern __shared__ uint32_t smw[];
    uint32_t* sQ  = smw;
    uint32_t* sKP = smw + ASM_Q;
    uint32_t* sV  = smw + ASM_Q + ASM_KP;

    const int qt  = blockIdx.x;
    const int bh  = blockIdx.y;
    const int tid = threadIdx.x;
    const int wid = tid >> 5;
    const int lane = tid & 31;
    const int qr = lane >> 2;
    const int ql = lane & 3;
    const int wm = wid * 16;

    {
        const float* Qg = Q + ((size_t)bh * S_ + qt * 64) * DK_;
#pragma unroll
        for (int it = 0; it < 8; ++it) {
            int f = tid + it * 128;
            int row = f >> 4;
            int c4  = (f & 15) << 2;
            float4 v = *(const float4*)(Qg + row * 64 + c4);
            uint32_t* d = &sQ[row * ASTR_QKP + c4];
            d[0] = f2tf32(v.x); d[1] = f2tf32(v.y);
            d[2] = f2tf32(v.z); d[3] = f2tf32(v.w);
        }
    }

    float mrow0 = -1e30f, mrow1 = -1e30f, lrow0 = 0.f, lrow1 = 0.f;
    float o[8][4];
#pragma unroll
    for (int nt = 0; nt < 8; ++nt)
#pragma unroll
        for (int e = 0; e < 4; ++e) o[nt][e] = 0.f;

    for (int t = 0; t <= qt; ++t) {
        __syncthreads();
        const float* Kg = K + ((size_t)bh * S_ + t * 64) * DK_;
        const float* Vg = V + ((size_t)bh * S_ + t * 64) * DK_;
#pragma unroll
        for (int it = 0; it < 8; ++it) {
            int f = tid + it * 128;
            int row = f >> 4;
            int c4  = (f & 15) << 2;
            float4 kv4 = *(const float4*)(Kg + row * 64 + c4);
            uint32_t* dk_ = &sKP[row * ASTR_QKP + c4];
            dk_[0] = f2tf32(kv4.x); dk_[1] = f2tf32(kv4.y);
            dk_[2] = f2tf32(kv4.z); dk_[3] = f2tf32(kv4.w);
            float4 vv4 = *(const float4*)(Vg + row * 64 + c4);
            uint32_t* dv_ = &sV[row * ASTR_V + c4];
            dv_[0] = f2tf32(vv4.x); dv_[1] = f2tf32(vv4.y);
            dv_[2] = f2tf32(vv4.z); dv_[3] = f2tf32(vv4.w);
        }
        __syncthreads();

        float sc[8][4];
#pragma unroll
        for (int nt = 0; nt < 8; ++nt)
#pragma unroll
            for (int e = 0; e < 4; ++e) sc[nt][e] = 0.f;

#pragma unroll
        for (int k0 = 0; k0 < 64; k0 += 8) {
            uint32_t a[4];
            a[0] = sQ[(wm + qr    ) * ASTR_QKP + k0 + ql];
            a[1] = sQ[(wm + qr + 8) * ASTR_QKP + k0 + ql];
            a[2] = sQ[(wm + qr    ) * ASTR_QKP + k0 + ql + 4];
            a[3] = sQ[(wm + qr + 8) * ASTR_QKP + k0 + ql + 4];
#pragma unroll
            for (int nt = 0; nt < 8; ++nt) {
                uint32_t b[2];
                b[0] = sKP[(nt * 8 + qr) * ASTR_QKP + k0 + ql];
                b[1] = sKP[(nt * 8 + qr) * ASTR_QKP + k0 + ql + 4];
                mma_tf32(sc[nt], a, b);
            }
        }
        __syncthreads();

        const int r0l = wm + qr, r1l = wm + qr + 8;
        float tm0 = -1e30f, tm1 = -1e30f;
#pragma unroll
        for (int nt = 0; nt < 8; ++nt) {
            const int c0 = nt * 8 + 2 * ql, c1 = c0 + 1;
#pragma unroll
            for (int e = 0; e < 4; ++e) sc[nt][e] *= 0.125f;
            if (t == qt) {
                if (c0 > r0l) sc[nt][0] = -1e9f;
                if (c1 > r0l) sc[nt][1] = -1e9f;
                if (c0 > r1l) sc[nt][2] = -1e9f;
                if (c1 > r1l) sc[nt][3] = -1e9f;
            }
            tm0 = fmaxf(tm0, fmaxf(sc[nt][0], sc[nt][1]));
            tm1 = fmaxf(tm1, fmaxf(sc[nt][2], sc[nt][3]));
        }
        tm0 = fmaxf(tm0, __shfl_xor_sync(0xffffffffu, tm0, 1));
        tm0 = fmaxf(tm0, __shfl_xor_sync(0xffffffffu, tm0, 2));
        tm1 = fmaxf(tm1, __shfl_xor_sync(0xffffffffu, tm1, 1));
        tm1 = fmaxf(tm1, __shfl_xor_sync(0xffffffffu, tm1, 2));

        const float nm0 = fmaxf(mrow0, tm0);
        const float nm1 = fmaxf(mrow1, tm1);
        const float al0 = __expf(mrow0 - nm0);
        const float al1 = __expf(mrow1 - nm1);
        float sum0 = 0.f, sum1 = 0.f;
#pragma unroll
        for (int nt = 0; nt < 8; ++nt) {
            sc[nt][0] = __expf(sc[nt][0] - nm0);
            sc[nt][1] = __expf(sc[nt][1] - nm0);
            sc[nt][2] = __expf(sc[nt][2] - nm1);
            sc[nt][3] = __expf(sc[nt][3] - nm1);
            sum0 += sc[nt][0] + sc[nt][1];
            sum1 += sc[nt][2] + sc[nt][3];
        }
        sum0 += __shfl_xor_sync(0xffffffffu, sum0, 1);
        sum0 += __shfl_xor_sync(0xffffffffu, sum0, 2);
        sum1 += __shfl_xor_sync(0xffffffffu, sum1, 1);
        sum1 += __shfl_xor_sync(0xffffffffu, sum1, 2);

        lrow0 = lrow0 * al0 + sum0;
        lrow1 = lrow1 * al1 + sum1;
        mrow0 = nm0; mrow1 = nm1;

#pragma unroll
        for (int nt = 0; nt < 8; ++nt) {
            o[nt][0] *= al0; o[nt][1] *= al0;
            o[nt][2] *= al1; o[nt][3] *= al1;
        }

#pragma unroll
        for (int nt = 0; nt < 8; ++nt) {
            const int base0 = (wm + qr) * ASTR_QKP + nt * 8 + 2 * ql;
            sKP[base0]     = f2tf32(sc[nt][0]);
            sKP[base0 + 1] = f2tf32(sc[nt][1]);
            const int base1 = base0 + 8 * ASTR_QKP;
            sKP[base1]     = f2tf32(sc[nt][2]);
            sKP[base1 + 1] = f2tf32(sc[nt][3]);
        }
        __syncwarp();

#pragma unroll
        for (int k0 = 0; k0 < 64; k0 += 8) {
            uint32_t a[4];
            a[0] = sKP[(wm + qr    ) * ASTR_QKP + k0 + ql];
            a[1] = sKP[(wm + qr + 8) * ASTR_QKP + k0 + ql];
            a[2] = sKP[(wm + qr    ) * ASTR_QKP + k0 + ql + 4];
            a[3] = sKP[(wm + qr + 8) * ASTR_QKP + k0 + ql + 4];
#pragma unroll
            for (int nt = 0; nt < 8; ++nt) {
                uint32_t b[2];
                b[0] = sV[(k0 + ql    ) * ASTR_V + nt * 8 + qr];
                b[1] = sV[(k0 + ql + 4) * ASTR_V + nt * 8 + qr];
                mma_tf32(o[nt], a, b);
            }
        }
    }

    const float i0 = 1.f / lrow0, i1 = 1.f / lrow1;
    const int b = bh >> 4, h = bh & 15;
    const int s0 = qt * 64 + wm + qr, s1 = s0 + 8;
#pragma unroll
    for (int nt = 0; nt < 8; ++nt) {
        const int dk = nt * 8 + 2 * ql;
        float* p0 = Out + ((size_t)(b * S_ + s0)) * D_ + h * DK_ + dk;
        *(float2*)p0 = make_float2(o[nt][0] * i0, o[nt][1] * i0);
        float* p1 = Out + ((size_t)(b * S_ + s1)) * D_ + h * DK_ + dk;
        *(float2*)p1 = make_float2(o[nt][2] * i1, o[nt][3] * i1);
    }
}

// ============================================================================
// Launch
// ============================================================================
extern "C" void kernel_launch(void* const* d_in, const int* in_sizes, int n_in,
                              void* d_out, int out_size) {
    const float* q  = (const float*)d_in[0];
    const float* k  = (const float*)d_in[1];
    const float* v  = (const float*)d_in[2];
    // d_in[3] = mask (causal, known statically) — unused
    const float* Wq = (const float*)d_in[4];
    const float* Wk = (const float*)d_in[5];
    const float* Wv = (const float*)d_in[6];
    const float* Wo = (const float*)d_in[7];
    float* out = (float*)d_out;

    float *pQ, *pK, *pV, *pA;
    cudaGetSymbolAddress((void**)&pQ, g_Q);
    cudaGetSymbolAddress((void**)&pK, g_K);
    cudaGetSymbolAddress((void**)&pV, g_V);
    cudaGetSymbolAddress((void**)&pA, g_A);

    cudaFuncSetAttribute(gemm_qkv, cudaFuncAttributeMaxDynamicSharedMemorySize, GEMM_SMEM);
    cudaFuncSetAttribute(gemm_out, cudaFuncAttributeMaxDynamicSharedMemorySize, GEMM_SMEM);
    cudaFuncSetAttribute(attn_mma, cudaFuncAttributeMaxDynamicSharedMemorySize, ATT_SMEM);

    dim3 qkv_grid(D_ / BN, M_ / BM, 3);   // (4, 64, 3)
    gemm_qkv<<<qkv_grid, 256, GEMM_SMEM>>>(q, k, v, Wq, Wk, Wv, pQ, pK, pV);

    attn_mma<<<dim3(S_ / 64, B_ * H_), 128, ATT_SMEM>>>(pQ, pK, pV, pA);

    dim3 ogrid(D_ / BN, M_ / BM);         // (4, 64)
    gemm_out<<<ogrid, 256, GEMM_SMEM>>>(pA, Wo, out);
}